// round 1
// baseline (speedup 1.0000x reference)
#include <cuda_runtime.h>
#include <cuda_bf16.h>
#include <math.h>

#define ND 10000
#define EMAX 1000000

// ---------------- device scratch (static globals; no runtime allocation) ----
__device__ int   g_cnt_b[ND];
__device__ int   g_cnt_t[ND];
__device__ int   g_off_b[ND];
__device__ int   g_off_t[ND];
__device__ int   g_cur_b[ND];
__device__ int   g_cur_t[ND];
__device__ int   g_sorted_b[EMAX];   // resolved emb ids, grouped by dst
__device__ int   g_sorted_t[EMAX];
__device__ float g_B[ND * 64];       // sum of relu(bene rows) per diag node
__device__ float g_T[ND * 64];       // sum of relu(treat rows) per diag node
__device__ float g_score[ND];        // final per-diag-node score

// ---------------- 1) zero the histograms ------------------------------------
__global__ void zero_kernel() {
    int i = blockIdx.x * blockDim.x + threadIdx.x;
    int stride = gridDim.x * blockDim.x;
    for (; i < 2 * ND; i += stride) {
        if (i < ND) g_cnt_b[i] = 0;
        else        g_cnt_t[i - ND] = 0;
    }
}

// ---------------- 2) histogram over both edge sets --------------------------
__global__ void hist_kernel(const int* __restrict__ dstb,
                            const int* __restrict__ dstt, int n) {
    int i = blockIdx.x * blockDim.x + threadIdx.x;
    int stride = gridDim.x * blockDim.x;
    for (; i < 2 * n; i += stride) {
        if (i < n) atomicAdd(&g_cnt_b[dstb[i]], 1);
        else       atomicAdd(&g_cnt_t[dstt[i - n]], 1);
    }
}

// ---------------- 3) exclusive scan of both histograms (single block) -------
__global__ void scan2_kernel() {
    __shared__ int sh[1024];
    __shared__ int carry;
    for (int which = 0; which < 2; which++) {
        const int* cnt = which ? g_cnt_t : g_cnt_b;
        int* off = which ? g_off_t : g_off_b;
        int* cur = which ? g_cur_t : g_cur_b;
        if (threadIdx.x == 0) carry = 0;
        __syncthreads();
        for (int base = 0; base < ND; base += 1024) {
            int i = base + (int)threadIdx.x;
            int v = (i < ND) ? cnt[i] : 0;
            sh[threadIdx.x] = v;
            __syncthreads();
            // Hillis-Steele inclusive scan (in place, double-sync)
            for (int d = 1; d < 1024; d <<= 1) {
                int t = (threadIdx.x >= (unsigned)d) ? sh[threadIdx.x - d] : 0;
                __syncthreads();
                sh[threadIdx.x] += t;
                __syncthreads();
            }
            int excl = sh[threadIdx.x] - v + carry;
            if (i < ND) { off[i] = excl; cur[i] = excl; }
            int chunk_total = sh[1023];
            __syncthreads();
            if (threadIdx.x == 0) carry += chunk_total;
            __syncthreads();
        }
    }
}

// ---------------- 4) scatter: bucket edges by dst, store resolved emb id ----
__global__ void scatter_kernel(const int* __restrict__ src,
                               const int* __restrict__ dst,
                               const int* __restrict__ ids,
                               int n, int which) {
    int* cur = which ? g_cur_t : g_cur_b;
    int* out = which ? g_sorted_t : g_sorted_b;
    int i = blockIdx.x * blockDim.x + threadIdx.x;
    int stride = gridDim.x * blockDim.x;
    for (; i < n; i += stride) {
        int d = dst[i];
        int p = atomicAdd(&cur[d], 1);
        out[p] = ids[src[i]];
    }
}

// ---------------- 5) segment aggregation: one warp per dst node -------------
// acc[d] = sum over segment of relu(emb[id]);  lane holds 2 columns (float2).
__global__ void agg_kernel(const float* __restrict__ emb_b,
                           const float* __restrict__ emb_t) {
    int gw = (blockIdx.x * blockDim.x + threadIdx.x) >> 5;
    int lane = threadIdx.x & 31;
    if (gw >= 2 * ND) return;
    int which = (gw >= ND);
    int d = which ? (gw - ND) : gw;
    const int* off = which ? g_off_t : g_off_b;
    const int* cnt = which ? g_cnt_t : g_cnt_b;
    const int* srt = which ? g_sorted_t : g_sorted_b;
    const float* emb = which ? emb_t : emb_b;
    float* out = which ? g_T : g_B;

    int s = off[d];
    int n = cnt[d];
    float ax = 0.f, ay = 0.f;
    int i = 0;
    for (; i + 4 <= n; i += 4) {
        int i0 = srt[s + i + 0];
        int i1 = srt[s + i + 1];
        int i2 = srt[s + i + 2];
        int i3 = srt[s + i + 3];
        float2 v0 = __ldg((const float2*)(emb + (size_t)i0 * 64) + lane);
        float2 v1 = __ldg((const float2*)(emb + (size_t)i1 * 64) + lane);
        float2 v2 = __ldg((const float2*)(emb + (size_t)i2 * 64) + lane);
        float2 v3 = __ldg((const float2*)(emb + (size_t)i3 * 64) + lane);
        ax += fmaxf(v0.x, 0.f); ay += fmaxf(v0.y, 0.f);
        ax += fmaxf(v1.x, 0.f); ay += fmaxf(v1.y, 0.f);
        ax += fmaxf(v2.x, 0.f); ay += fmaxf(v2.y, 0.f);
        ax += fmaxf(v3.x, 0.f); ay += fmaxf(v3.y, 0.f);
    }
    for (; i < n; i++) {
        int id = srt[s + i];
        float2 v = __ldg((const float2*)(emb + (size_t)id * 64) + lane);
        ax += fmaxf(v.x, 0.f); ay += fmaxf(v.y, 0.f);
    }
    float2 r; r.x = ax; r.y = ay;
    ((float2*)(out + (size_t)d * 64))[lane] = r;
}

// ---------------- 6) fused per-node head -----------------------------------
// C = 0.5*(B@Wb1 + degb*bb1 + T@Wt1 + degt*bt1)
// D = relu(C@Wu1 + bu1); h = relu(D@oW1 + ob1); score = sigmoid(h.oW2 + ob2)
// block = 256 threads = 4 groups of 64; grid = 250 (10000 rows, 10 iters each)
__global__ void head_kernel(const float* __restrict__ Wb, const float* __restrict__ bb,
                            const float* __restrict__ Wt, const float* __restrict__ bt,
                            const float* __restrict__ Wu, const float* __restrict__ bu,
                            const float* __restrict__ oW1, const float* __restrict__ ob1,
                            const float* __restrict__ oW2, const float* __restrict__ ob2) {
    __shared__ float sWb[64 * 64];
    __shared__ float sWt[64 * 64];
    __shared__ float sbb[64], sbt[64], sbu[64];
    __shared__ float sB[4][64], sT[4][64], sC[4][64], sD[4][64];

    int tid = threadIdx.x;
    for (int k = tid; k < 4096; k += 256) { sWb[k] = Wb[k]; sWt[k] = Wt[k]; }
    if (tid < 64) { sbb[tid] = bb[tid]; sbt[tid] = bt[tid]; sbu[tid] = bu[tid]; }
    __syncthreads();

    int grp = tid >> 6;
    int j   = tid & 63;

    // grid 250 * 4 groups = 1000 row-slots, stride 1000, exactly 10 iterations
    for (int row = blockIdx.x * 4 + grp; row < ND; row += gridDim.x * 4) {
        sB[grp][j] = g_B[(size_t)row * 64 + j];
        sT[grp][j] = g_T[(size_t)row * 64 + j];
        float degb = (float)g_cnt_b[row];
        float degt = (float)g_cnt_t[row];
        __syncthreads();

        float c = 0.f;
        #pragma unroll 16
        for (int k = 0; k < 64; k++) {
            c += sB[grp][k] * sWb[k * 64 + j];
            c += sT[grp][k] * sWt[k * 64 + j];
        }
        c = 0.5f * (c + degb * sbb[j] + degt * sbt[j]);
        sC[grp][j] = c;
        __syncthreads();

        float dd = sbu[j];
        #pragma unroll 16
        for (int k = 0; k < 64; k++)
            dd += sC[grp][k] * __ldg(&Wu[k * 64 + j]);
        sD[grp][j] = fmaxf(dd, 0.f);
        __syncthreads();

        if (j < 32) {
            float h = __ldg(&ob1[j]);
            #pragma unroll 16
            for (int k = 0; k < 64; k++)
                h += sD[grp][k] * __ldg(&oW1[k * 32 + j]);
            h = fmaxf(h, 0.f);
            float p = h * __ldg(&oW2[j]);
            #pragma unroll
            for (int o = 16; o > 0; o >>= 1)
                p += __shfl_down_sync(0xffffffffu, p, o);
            if (j == 0)
                g_score[row] = 1.f / (1.f + expf(-(p + __ldg(ob2))));
        }
        __syncthreads();
    }
}

// ---------------- 7) output gather ------------------------------------------
__global__ void out_gather_kernel(const int* __restrict__ inst2type,
                                  float* __restrict__ out, int n) {
    int i = blockIdx.x * blockDim.x + threadIdx.x;
    int stride = gridDim.x * blockDim.x;
    for (; i < n; i += stride)
        out[i] = g_score[inst2type[i]];
}

// ---------------- launch ------------------------------------------------------
extern "C" void kernel_launch(void* const* d_in, const int* in_sizes, int n_in,
                              void* d_out, int out_size) {
    const int*   bene_ids      = (const int*)d_in[0];
    const int*   treatment_ids = (const int*)d_in[2];
    const int*   b2d_src       = (const int*)d_in[3];
    const int*   b2d_dst       = (const int*)d_in[4];
    const int*   t2d_src       = (const int*)d_in[5];
    const int*   t2d_dst       = (const int*)d_in[6];
    const int*   inst2type     = (const int*)d_in[7];
    const float* bene_emb      = (const float*)d_in[8];
    const float* treat_emb     = (const float*)d_in[10];
    // layer-0 weights (indices 11..16) are dead code — never read
    const float* Wb1 = (const float*)d_in[17];
    const float* bb1 = (const float*)d_in[18];
    const float* Wt1 = (const float*)d_in[19];
    const float* bt1 = (const float*)d_in[20];
    const float* Wu1 = (const float*)d_in[21];
    const float* bu1 = (const float*)d_in[22];
    const float* oW1 = (const float*)d_in[23];
    const float* ob1 = (const float*)d_in[24];
    const float* oW2 = (const float*)d_in[25];
    const float* ob2 = (const float*)d_in[26];

    int E     = in_sizes[3];
    int NINST = in_sizes[7];

    zero_kernel<<<40, 256>>>();
    hist_kernel<<<1024, 256>>>(b2d_dst, t2d_dst, E);
    scan2_kernel<<<1, 1024>>>();
    scatter_kernel<<<1024, 256>>>(b2d_src, b2d_dst, bene_ids, E, 0);
    scatter_kernel<<<1024, 256>>>(t2d_src, t2d_dst, treatment_ids, E, 1);
    {
        int warps = 2 * ND;                 // one warp per (edge-set, dst) segment
        int blocks = (warps * 32 + 255) / 256;
        agg_kernel<<<blocks, 256>>>(bene_emb, treat_emb);
    }
    head_kernel<<<250, 256>>>(Wb1, bb1, Wt1, bt1, Wu1, bu1, oW1, ob1, oW2, ob2);
    out_gather_kernel<<<(NINST + 255) / 256, 256>>>(inst2type, (float*)d_out, NINST);
}

// round 2
// speedup vs baseline: 1.0942x; 1.0942x over previous
#include <cuda_runtime.h>
#include <cuda_bf16.h>
#include <math.h>

#define ND 10000
#define EMAX 1000000
#define NB_EMB 10000   // bene emb rows
#define NT_EMB 1000    // treat emb rows
#define H 64

// ---------------- device scratch ---------------------------------------------
__device__ int   g_cnt_b[ND];
__device__ int   g_cnt_t[ND];
__device__ int   g_off_b[ND];
__device__ int   g_off_t[ND];
__device__ int   g_cur_b[ND];
__device__ int   g_cur_t[ND];
__device__ int   g_sorted_b[EMAX];
__device__ int   g_sorted_t[EMAX];
__device__ __nv_bfloat16 g_Rb[NB_EMB * H];  // relu(bene_emb) in bf16
__device__ __nv_bfloat16 g_Rt[NT_EMB * H];  // relu(treat_emb) in bf16
__device__ float g_B[ND * H];
__device__ float g_T[ND * H];
__device__ float g_score[ND];

// ---------------- 1) prep: zero counters + relu+bf16 convert emb tables ------
__global__ void prep_kernel(const float* __restrict__ be,
                            const float* __restrict__ te) {
    int tid = blockIdx.x * blockDim.x + threadIdx.x;
    int stride = gridDim.x * blockDim.x;
    for (int i = tid; i < 2 * ND; i += stride) {
        if (i < ND) g_cnt_b[i] = 0;
        else        g_cnt_t[i - ND] = 0;
    }
    for (int i = tid; i < NB_EMB * H; i += stride)
        g_Rb[i] = __float2bfloat16(fmaxf(be[i], 0.f));
    for (int i = tid; i < NT_EMB * H; i += stride)
        g_Rt[i] = __float2bfloat16(fmaxf(te[i], 0.f));
}

// ---------------- 2) histogram, both edge sets, int4-vectorized --------------
__global__ void hist_kernel(const int* __restrict__ dstb,
                            const int* __restrict__ dstt, int n) {
    int n4 = n >> 2;
    int total = 2 * n4;
    int g = blockIdx.x * blockDim.x + threadIdx.x;
    int stride = gridDim.x * blockDim.x;
    for (int i = g; i < total; i += stride) {
        int which = (i >= n4);
        int gg = which ? i - n4 : i;
        const int4* d4 = (const int4*)(which ? dstt : dstb);
        int* cnt = which ? g_cnt_t : g_cnt_b;
        int4 d = d4[gg];
        atomicAdd(&cnt[d.x], 1);
        atomicAdd(&cnt[d.y], 1);
        atomicAdd(&cnt[d.z], 1);
        atomicAdd(&cnt[d.w], 1);
    }
    // tail (n not multiple of 4)
    int rem = n & 3;
    if (g < rem) {
        atomicAdd(&g_cnt_b[dstb[n - 1 - g]], 1);
        atomicAdd(&g_cnt_t[dstt[n - 1 - g]], 1);
    }
}

// ---------------- 3) exclusive scan, thread-coarsened + shuffle --------------
__global__ void scan_kernel() {
    const int PER = 10;  // 1024 * 10 = 10240 >= ND
    __shared__ int wsum[32];
    int lane = threadIdx.x & 31;
    int wid = threadIdx.x >> 5;
    for (int which = 0; which < 2; which++) {
        const int* cnt = which ? g_cnt_t : g_cnt_b;
        int* off = which ? g_off_t : g_off_b;
        int* cur = which ? g_cur_t : g_cur_b;
        int base = threadIdx.x * PER;
        int local[PER];
        int sum = 0;
        #pragma unroll
        for (int k = 0; k < PER; k++) {
            int idx = base + k;
            int v = (idx < ND) ? cnt[idx] : 0;
            local[k] = sum;  // exclusive within thread
            sum += v;
        }
        // warp inclusive scan of thread totals
        int inc = sum;
        #pragma unroll
        for (int o = 1; o < 32; o <<= 1) {
            int t = __shfl_up_sync(0xffffffffu, inc, o);
            if (lane >= o) inc += t;
        }
        if (lane == 31) wsum[wid] = inc;
        __syncthreads();
        if (wid == 0) {
            int w = wsum[lane];
            #pragma unroll
            for (int o = 1; o < 32; o <<= 1) {
                int t = __shfl_up_sync(0xffffffffu, w, o);
                if (lane >= o) w += t;
            }
            wsum[lane] = w;
        }
        __syncthreads();
        int thread_off = inc - sum + (wid > 0 ? wsum[wid - 1] : 0);
        #pragma unroll
        for (int k = 0; k < PER; k++) {
            int idx = base + k;
            if (idx < ND) {
                int e = thread_off + local[k];
                off[idx] = e;
                cur[idx] = e;
            }
        }
        __syncthreads();
    }
}

// ---------------- 4) scatter, both edge sets, 4-way pipelined ----------------
__global__ void scatter_kernel(const int* __restrict__ srcb, const int* __restrict__ dstb,
                               const int* __restrict__ idsb,
                               const int* __restrict__ srct, const int* __restrict__ dstt,
                               const int* __restrict__ idst, int n) {
    int n4 = n >> 2;
    int total = 2 * n4;
    int g = blockIdx.x * blockDim.x + threadIdx.x;
    int stride = gridDim.x * blockDim.x;
    for (int i = g; i < total; i += stride) {
        int which = (i >= n4);
        int gg = which ? i - n4 : i;
        const int4* s4 = (const int4*)(which ? srct : srcb);
        const int4* d4 = (const int4*)(which ? dstt : dstb);
        const int* ids = which ? idst : idsb;
        int* cur = which ? g_cur_t : g_cur_b;
        int* out = which ? g_sorted_t : g_sorted_b;
        int4 d = d4[gg];
        int4 s = s4[gg];
        // 4 independent atomics in flight
        int p0 = atomicAdd(&cur[d.x], 1);
        int p1 = atomicAdd(&cur[d.y], 1);
        int p2 = atomicAdd(&cur[d.z], 1);
        int p3 = atomicAdd(&cur[d.w], 1);
        int v0 = __ldg(&ids[s.x]);
        int v1 = __ldg(&ids[s.y]);
        int v2 = __ldg(&ids[s.z]);
        int v3 = __ldg(&ids[s.w]);
        out[p0] = v0;
        out[p1] = v1;
        out[p2] = v2;
        out[p3] = v3;
    }
    int rem = n & 3;
    if (g < rem) {
        int i = n - 1 - g;
        int pb = atomicAdd(&g_cur_b[dstb[i]], 1);
        g_sorted_b[pb] = idsb[srcb[i]];
        int pt = atomicAdd(&g_cur_t[dstt[i]], 1);
        g_sorted_t[pt] = idst[srct[i]];
    }
}

// ---------------- 5) segment aggregation: one warp per segment, bf16 reads ---
__global__ void agg_kernel() {
    int gw = (blockIdx.x * blockDim.x + threadIdx.x) >> 5;
    int lane = threadIdx.x & 31;
    if (gw >= 2 * ND) return;
    int which = (gw >= ND);
    int d = which ? (gw - ND) : gw;
    const int* off = which ? g_off_t : g_off_b;
    const int* cnt = which ? g_cnt_t : g_cnt_b;
    const int* srt = which ? g_sorted_t : g_sorted_b;
    const __nv_bfloat16* emb = which ? g_Rt : g_Rb;
    float* out = which ? g_T : g_B;

    int s = off[d];
    int n = cnt[d];
    float ax = 0.f, ay = 0.f;
    int i = 0;
    for (; i + 8 <= n; i += 8) {
        int id[8];
        #pragma unroll
        for (int k = 0; k < 8; k++) id[k] = __ldg(&srt[s + i + k]);
        __nv_bfloat162 v[8];
        #pragma unroll
        for (int k = 0; k < 8; k++)
            v[k] = __ldg((const __nv_bfloat162*)(emb + (size_t)id[k] * H) + lane);
        #pragma unroll
        for (int k = 0; k < 8; k++) {
            float2 f = __bfloat1622float2(v[k]);
            ax += f.x; ay += f.y;
        }
    }
    for (; i < n; i++) {
        int id = __ldg(&srt[s + i]);
        float2 f = __bfloat1622float2(
            __ldg((const __nv_bfloat162*)(emb + (size_t)id * H) + lane));
        ax += f.x; ay += f.y;
    }
    float2 r; r.x = ax; r.y = ay;
    ((float2*)(out + (size_t)d * H))[lane] = r;
}

// ---------------- 6) fused per-node head -------------------------------------
__global__ void head_kernel(const float* __restrict__ Wb, const float* __restrict__ bb,
                            const float* __restrict__ Wt, const float* __restrict__ bt,
                            const float* __restrict__ Wu, const float* __restrict__ bu,
                            const float* __restrict__ oW1, const float* __restrict__ ob1,
                            const float* __restrict__ oW2, const float* __restrict__ ob2) {
    __shared__ float sWb[64 * 64];
    __shared__ float sWt[64 * 64];
    __shared__ float sbb[64], sbt[64], sbu[64];
    __shared__ float sB[4][64], sT[4][64], sC[4][64], sD[4][64];

    int tid = threadIdx.x;
    for (int k = tid; k < 4096; k += 256) { sWb[k] = Wb[k]; sWt[k] = Wt[k]; }
    if (tid < 64) { sbb[tid] = bb[tid]; sbt[tid] = bt[tid]; sbu[tid] = bu[tid]; }
    __syncthreads();

    int grp = tid >> 6;
    int j   = tid & 63;

    for (int row = blockIdx.x * 4 + grp; row < ND; row += gridDim.x * 4) {
        sB[grp][j] = g_B[(size_t)row * 64 + j];
        sT[grp][j] = g_T[(size_t)row * 64 + j];
        float degb = (float)g_cnt_b[row];
        float degt = (float)g_cnt_t[row];
        __syncthreads();

        float c = 0.f;
        #pragma unroll 16
        for (int k = 0; k < 64; k++) {
            c += sB[grp][k] * sWb[k * 64 + j];
            c += sT[grp][k] * sWt[k * 64 + j];
        }
        c = 0.5f * (c + degb * sbb[j] + degt * sbt[j]);
        sC[grp][j] = c;
        __syncthreads();

        float dd = sbu[j];
        #pragma unroll 16
        for (int k = 0; k < 64; k++)
            dd += sC[grp][k] * __ldg(&Wu[k * 64 + j]);
        sD[grp][j] = fmaxf(dd, 0.f);
        __syncthreads();

        if (j < 32) {
            float h = __ldg(&ob1[j]);
            #pragma unroll 16
            for (int k = 0; k < 64; k++)
                h += sD[grp][k] * __ldg(&oW1[k * 32 + j]);
            h = fmaxf(h, 0.f);
            float p = h * __ldg(&oW2[j]);
            #pragma unroll
            for (int o = 16; o > 0; o >>= 1)
                p += __shfl_down_sync(0xffffffffu, p, o);
            if (j == 0)
                g_score[row] = 1.f / (1.f + expf(-(p + __ldg(ob2))));
        }
        __syncthreads();
    }
}

// ---------------- 7) output gather, float4 writes ----------------------------
__global__ void out_gather_kernel(const int* __restrict__ inst2type,
                                  float* __restrict__ out, int n) {
    int n4 = n >> 2;
    int i = blockIdx.x * blockDim.x + threadIdx.x;
    int stride = gridDim.x * blockDim.x;
    for (int g = i; g < n4; g += stride) {
        int4 t = ((const int4*)inst2type)[g];
        float4 r;
        r.x = g_score[t.x];
        r.y = g_score[t.y];
        r.z = g_score[t.z];
        r.w = g_score[t.w];
        ((float4*)out)[g] = r;
    }
    int rem = n & 3;
    if (i < rem)
        out[n - 1 - i] = g_score[inst2type[n - 1 - i]];
}

// ---------------- launch ------------------------------------------------------
extern "C" void kernel_launch(void* const* d_in, const int* in_sizes, int n_in,
                              void* d_out, int out_size) {
    const int*   bene_ids      = (const int*)d_in[0];
    const int*   treatment_ids = (const int*)d_in[2];
    const int*   b2d_src       = (const int*)d_in[3];
    const int*   b2d_dst       = (const int*)d_in[4];
    const int*   t2d_src       = (const int*)d_in[5];
    const int*   t2d_dst       = (const int*)d_in[6];
    const int*   inst2type     = (const int*)d_in[7];
    const float* bene_emb      = (const float*)d_in[8];
    const float* treat_emb     = (const float*)d_in[10];
    const float* Wb1 = (const float*)d_in[17];
    const float* bb1 = (const float*)d_in[18];
    const float* Wt1 = (const float*)d_in[19];
    const float* bt1 = (const float*)d_in[20];
    const float* Wu1 = (const float*)d_in[21];
    const float* bu1 = (const float*)d_in[22];
    const float* oW1 = (const float*)d_in[23];
    const float* ob1 = (const float*)d_in[24];
    const float* oW2 = (const float*)d_in[25];
    const float* ob2 = (const float*)d_in[26];

    int E     = in_sizes[3];
    int NINST = in_sizes[7];

    prep_kernel<<<160, 256>>>(bene_emb, treat_emb);
    {
        int n4 = E >> 2;
        int blocks = (2 * n4 + 255) / 256;
        if (blocks > 2048) blocks = 2048;
        if (blocks < 1) blocks = 1;
        hist_kernel<<<blocks, 256>>>(b2d_dst, t2d_dst, E);
        scan_kernel<<<1, 1024>>>();
        scatter_kernel<<<blocks, 256>>>(b2d_src, b2d_dst, bene_ids,
                                        t2d_src, t2d_dst, treatment_ids, E);
    }
    {
        int warps = 2 * ND;
        int blocks = (warps * 32 + 255) / 256;
        agg_kernel<<<blocks, 256>>>();
    }
    head_kernel<<<250, 256>>>(Wb1, bb1, Wt1, bt1, Wu1, bu1, oW1, ob1, oW2, ob2);
    {
        int blocks = ((NINST >> 2) + 255) / 256;
        if (blocks < 1) blocks = 1;
        out_gather_kernel<<<blocks, 256>>>(inst2type, (float*)d_out, NINST);
    }
}